// round 5
// baseline (speedup 1.0000x reference)
#include <cuda_runtime.h>
#include <cuda_bf16.h>
#include <math.h>

// ---------------------------------------------------------------------------
// NeuConV2Net: 3-plane back-projection + sim, 2x conv3x3, trilinear assemble
// Inputs (metadata order):
//  0 feat2d  (9,1,24,120,160) f32
//  1 KRcam   (9,1,4,4)        f32
//  2 vol_origin (1,3)         f32
//  3 w1 (96,24,3,3)  4 b1 (96)
//  5 w2 (288,96,3,3) 6 b2 (288)
// Output: feat (1,12,96,96,96) f32 then grid_mask (1,96,96,96) as f32
//
// Precision discipline: all fp32. The validity comparisons sit on EXACT
// lattice boundaries (e.g. y==0 iff iy+iz==16), so the projection must match
// the reference's rounding bit-for-bit:
//   - pts = origin + idx*0.04 as separate rounded mul/add (XLA elementwise)
//   - einsum row dot as UNFUSED mul/add ascending chain (XLA reduce fusion:
//     fmul/fadd, no fma contraction):
//       im = rn(rn(rn(k0*px) + rn(k1*py)) + rn(k2*pz)) + k3
// Everything else is value-continuous; ordering differences stay ~1e-7.
// ---------------------------------------------------------------------------

#define NVIEW 9
#define C2    24
#define IMH   120
#define IMW   160
#define NDOWN 24          // 96/4
#define SP    9216        // 96*96
#define PTS_PER_PLANE (NDOWN*SP)   // 221184
#define FEAT_N (12*96*96*96)       // 10616832
#define MASK_N (96*96*96)          // 884736

// scratch (device globals: no allocation allowed)
__device__ float g_featT[NVIEW*IMH*IMW*C2];     // NHWC transposed features
__device__ float g_vol [3*NDOWN*SP];            // sim volume, conv1 input layout
__device__ float g_cnt [3*NDOWN*SP];            // valid-view counts
__device__ float g_h1  [3*96*SP];               // conv1 output (relu)
__device__ float g_o2  [3*288*SP];              // conv2 output

// ---------------------------------------------------------------------------
// Kernel 0: (V,C,H,W) -> (V,H,W,C)
// ---------------------------------------------------------------------------
__global__ void k_transpose(const float* __restrict__ f)
{
    int p = blockIdx.x * blockDim.x + threadIdx.x;   // pixel over V*H*W
    if (p >= NVIEW*IMH*IMW) return;
    int v  = p / (IMH*IMW);
    int yx = p % (IMH*IMW);
    #pragma unroll
    for (int c = 0; c < C2; ++c)
        g_featT[p*C2 + c] = f[(v*C2 + c)*(IMH*IMW) + yx];
}

// einsum row dot: UNFUSED mul/add, ascending j, init 0 (XLA mul+reduce):
// t0=rn(k0*px); t=rn(t0+rn(k1*py)); t=rn(t+rn(k2*pz)); t=rn(t+rn(k3*1))
__device__ __forceinline__ float dot4(const float* __restrict__ k,
                                      float px, float py, float pz)
{
    float t = __fmul_rn(k[0], px);
    t = __fadd_rn(t, __fmul_rn(k[1], py));
    t = __fadd_rn(t, __fmul_rn(k[2], pz));
    t = __fadd_rn(t, k[3]);       // rn(k3*1) == k3 exactly
    return t;
}

// ---------------------------------------------------------------------------
// Kernel 1: back-projection + sim aggregation. One thread per point.
// ---------------------------------------------------------------------------
__global__ __launch_bounds__(128)
void k_backproject(const float* __restrict__ KR, const float* __restrict__ origin)
{
    __shared__ float sKR[NVIEW][12];   // rows 0..2 of each 4x4
    int tid = threadIdx.x;
    if (tid < NVIEW*12) {
        int v = tid / 12, e = tid % 12;
        sKR[v][e] = KR[v*16 + e];
    }
    __syncthreads();

    int gid = blockIdx.x * blockDim.x + tid;
    if (gid >= 3*PTS_PER_PLANE) return;

    int plane = gid / PTS_PER_PLANE;
    int r     = gid % PTS_PER_PLANE;
    int ch    = r / SP;
    int s     = r % SP;
    int s0    = s / 96;
    int s1    = s % 96;

    int ix, iy, iz;
    if (plane == 0)      { ix = 4*ch; iy = s0;   iz = s1;   }
    else if (plane == 1) { ix = s0;   iy = 4*ch; iz = s1;   }
    else                 { ix = s0;   iy = s1;   iz = 4*ch; }

    // XLA elementwise: separate rounded mul then add (NO fma contraction)
    float px = __fadd_rn(origin[0], __fmul_rn((float)ix, 0.04f));
    float py = __fadd_rn(origin[1], __fmul_rn((float)iy, 0.04f));
    float pz = __fadd_rn(origin[2], __fmul_rn((float)iz, 0.04f));

    float meanAcc[C2], snAcc[C2];
    #pragma unroll
    for (int c = 0; c < C2; ++c) { meanAcc[c] = 0.f; snAcc[c] = 0.f; }
    float cnt = 0.f;

    for (int v = 0; v < NVIEW; ++v) {
        float im0 = dot4(&sKR[v][0], px, py, pz);
        float im1 = dot4(&sKR[v][4], px, py, pz);
        float im2 = dot4(&sKR[v][8], px, py, pz);
        float zs = (fabsf(im2) < 1e-6f) ? 1e-6f : im2;
        float x = __fdiv_rn(im0, zs);
        float y = __fdiv_rn(im1, zs);
        bool valid = (im2 > 1e-3f) && (x >= 0.f) && (x <= (float)(IMW-1))
                                   && (y >= 0.f) && (y <= (float)(IMH-1));
        if (!valid) continue;
        cnt += 1.f;

        float x0 = fminf(fmaxf(floorf(x), 0.f), (float)(IMW-2));
        float y0 = fminf(fmaxf(floorf(y), 0.f), (float)(IMH-2));
        float wx = x - x0;
        float wy = y - y0;
        int xi = (int)x0, yi = (int)y0;

        float w00 = (1.f-wy)*(1.f-wx);
        float w01 = (1.f-wy)*wx;
        float w10 = wy*(1.f-wx);
        float w11 = wy*wx;

        const float* q00 = g_featT + ((v*IMH + yi)*IMW + xi)*C2;
        const float* q01 = q00 + C2;
        const float* q10 = q00 + IMW*C2;
        const float* q11 = q10 + C2;

        float sarr[C2];
        float nrm = 0.f;
        #pragma unroll
        for (int q = 0; q < C2/4; ++q) {
            float4 a = *(const float4*)(q00 + 4*q);
            float4 b = *(const float4*)(q01 + 4*q);
            float4 c = *(const float4*)(q10 + 4*q);
            float4 d = *(const float4*)(q11 + 4*q);
            float r0 = a.x*w00 + b.x*w01 + c.x*w10 + d.x*w11;
            float r1 = a.y*w00 + b.y*w01 + c.y*w10 + d.y*w11;
            float r2 = a.z*w00 + b.z*w01 + c.z*w10 + d.z*w11;
            float r3 = a.w*w00 + b.w*w01 + c.w*w10 + d.w*w11;
            sarr[4*q+0] = r0; sarr[4*q+1] = r1;
            sarr[4*q+2] = r2; sarr[4*q+3] = r3;
            nrm += r0*r0 + r1*r1 + r2*r2 + r3*r3;
        }
        float inv = 1.f / (sqrtf(nrm) + 1e-8f);
        #pragma unroll
        for (int c = 0; c < C2; ++c) {
            meanAcc[c] += sarr[c];
            snAcc[c]   += sarr[c] * inv;
        }
    }

    float denom = fmaxf(cnt, 1.f);
    float dot = 0.f, m2 = 0.f;
    #pragma unroll
    for (int c = 0; c < C2; ++c) {
        dot += snAcc[c] * meanAcc[c];
        m2  += meanAcc[c] * meanAcc[c];
    }
    // sim = (snAcc . mean) / (||mean|| + eps) / denom ; mean = meanAcc/denom
    float sim = dot / (denom * (sqrtf(m2)/denom + 1e-8f) * denom);

    g_vol[gid] = sim;
    g_cnt[gid] = cnt;
}

// ---------------------------------------------------------------------------
// Kernel 2: direct 3x3 SAME conv, smem tiled, 4oc x 4px register tile.
// grid: x = spatial tiles (6 x 24), y = OC/32, z = plane
// ---------------------------------------------------------------------------
#define CICB 8
#define COCT 32
#define CPW  16
#define CPH  4

template<int IC, int OC, bool RELU>
__global__ __launch_bounds__(128)
void k_conv3x3(const float* __restrict__ inBase, const float* __restrict__ w,
               const float* __restrict__ bias, float* __restrict__ outBase)
{
    const int plane = blockIdx.z;
    const float* in  = inBase  + plane * IC * SP;
    float*       out = outBase + plane * OC * SP;

    const int tile = blockIdx.x;
    const int tx0  = (tile % (96/CPW)) * CPW;
    const int ty0  = (tile / (96/CPW)) * CPH;
    const int ocg  = blockIdx.y * COCT;

    __shared__ float sIn[CICB][CPH+2][CPW+2];
    __shared__ float sW [COCT][CICB][9];

    const int tid = threadIdx.x;
    const int lx  = tid & 15;     // x within tile
    const int ocq = tid >> 4;     // 0..7 -> 4 out channels each

    float acc[4][4];
    #pragma unroll
    for (int j = 0; j < 4; ++j)
        #pragma unroll
        for (int yy = 0; yy < 4; ++yy) acc[j][yy] = 0.f;

    for (int ic0 = 0; ic0 < IC; ic0 += CICB) {
        __syncthreads();
        // input tile (with halo, zero padded)
        for (int e = tid; e < CICB*(CPH+2)*(CPW+2); e += 128) {
            int ic = e / ((CPH+2)*(CPW+2));
            int rr = e % ((CPH+2)*(CPW+2));
            int yy = rr / (CPW+2), xx = rr % (CPW+2);
            int gy = ty0 + yy - 1, gx = tx0 + xx - 1;
            float v = 0.f;
            if (gy >= 0 && gy < 96 && gx >= 0 && gx < 96)
                v = in[(ic0+ic)*SP + gy*96 + gx];
            sIn[ic][yy][xx] = v;
        }
        // weights
        for (int e = tid; e < COCT*CICB*9; e += 128) {
            int oc  = e / (CICB*9);
            int rr  = e % (CICB*9);
            int ic  = rr / 9, tap = rr % 9;
            sW[oc][ic][tap] = w[((ocg+oc)*IC + ic0+ic)*9 + tap];
        }
        __syncthreads();

        #pragma unroll
        for (int ic = 0; ic < CICB; ++ic) {
            #pragma unroll
            for (int dy = 0; dy < 3; ++dy) {
                #pragma unroll
                for (int dx = 0; dx < 3; ++dx) {
                    float iv[4];
                    #pragma unroll
                    for (int yy = 0; yy < 4; ++yy)
                        iv[yy] = sIn[ic][yy+dy][lx+dx];
                    #pragma unroll
                    for (int j = 0; j < 4; ++j) {
                        float wv = sW[ocq*4+j][ic][dy*3+dx];
                        #pragma unroll
                        for (int yy = 0; yy < 4; ++yy)
                            acc[j][yy] += iv[yy] * wv;
                    }
                }
            }
        }
    }

    #pragma unroll
    for (int j = 0; j < 4; ++j) {
        int oc = ocg + ocq*4 + j;
        float bb = bias[oc];
        #pragma unroll
        for (int yy = 0; yy < 4; ++yy) {
            float v = acc[j][yy] + bb;
            if (RELU) v = fmaxf(v, 0.f);
            out[oc*SP + (ty0+yy)*96 + (tx0+lx)] = v;
        }
    }
}

// ---------------------------------------------------------------------------
// Kernel 3: trilinear upsample (x4 along plane down-axis) + 3-plane sum
// jax.image.resize half-pixel: src = o/4 - 0.375, edge renorm == clamp.
// Weights dyadic-exact; value-continuous fp32.
// ---------------------------------------------------------------------------
__global__ void k_assemble(float* __restrict__ out, int out_size)
{
    int gid = blockIdx.x * blockDim.x + threadIdx.x;
    if (gid >= FEAT_N) return;
    int z = gid % 96;
    int y = (gid / 96) % 96;
    int x = (gid / SP) % 96;
    int t = gid / MASK_N;

    float acc;
    {   // plane 0: interp along a (x-axis) of o2_0[t*24+a][y][z]
        float s = fminf(fmaxf((float)x*0.25f - 0.375f, 0.f), 23.f);
        int i0 = (int)s; float f = s - (float)i0; int i1 = min(i0+1, 23);
        const float* p = g_o2 + (t*24)*SP + y*96 + z;
        acc = __fadd_rn(__fmul_rn(p[i0*SP], 1.f-f), __fmul_rn(p[i1*SP], f));
    }
    {   // plane 1: interp along b (y-axis) of o2_1[t*24+b][x][z]
        float s = fminf(fmaxf((float)y*0.25f - 0.375f, 0.f), 23.f);
        int i0 = (int)s; float f = s - (float)i0; int i1 = min(i0+1, 23);
        const float* p = g_o2 + 288*SP + (t*24)*SP + x*96 + z;
        acc = __fadd_rn(acc, __fadd_rn(__fmul_rn(p[i0*SP], 1.f-f), __fmul_rn(p[i1*SP], f)));
    }
    {   // plane 2: interp along c (z-axis) of o2_2[t*24+c][x][y]
        float s = fminf(fmaxf((float)z*0.25f - 0.375f, 0.f), 23.f);
        int i0 = (int)s; float f = s - (float)i0; int i1 = min(i0+1, 23);
        const float* p = g_o2 + 2*288*SP + (t*24)*SP + x*96 + y;
        acc = __fadd_rn(acc, __fadd_rn(__fmul_rn(p[i0*SP], 1.f-f), __fmul_rn(p[i1*SP], f)));
    }
    if (gid < out_size) out[gid] = acc;
}

// ---------------------------------------------------------------------------
// Kernel 4: grid mask: nearest(count) > 1 for any plane. nearest idx = o/4.
// ---------------------------------------------------------------------------
__global__ void k_mask(float* __restrict__ out, int out_size)
{
    int gid = blockIdx.x * blockDim.x + threadIdx.x;
    if (gid >= MASK_N) return;
    int z = gid % 96;
    int y = (gid / 96) % 96;
    int x = gid / SP;

    float c0 = g_cnt[              ((x >> 2)*96 + y)*96 + z];
    float c1 = g_cnt[  NDOWN*SP + ((y >> 2)*96 + x)*96 + z];
    float c2 = g_cnt[2*NDOWN*SP + ((z >> 2)*96 + x)*96 + y];
    float m = (c0 > 1.f || c1 > 1.f || c2 > 1.f) ? 1.f : 0.f;
    if (FEAT_N + gid < out_size) out[FEAT_N + gid] = m;
}

// ---------------------------------------------------------------------------
extern "C" void kernel_launch(void* const* d_in, const int* in_sizes, int n_in,
                              void* d_out, int out_size)
{
    const float* feat2d = (const float*)d_in[0];
    const float* KRcam  = (const float*)d_in[1];
    const float* origin = (const float*)d_in[2];
    const float* w1     = (const float*)d_in[3];
    const float* b1     = (const float*)d_in[4];
    const float* w2     = (const float*)d_in[5];
    const float* b2     = (const float*)d_in[6];
    float* out = (float*)d_out;

    // device-global scratch pointers
    float *vol, *h1, *o2;
    cudaGetSymbolAddress((void**)&vol,   g_vol);
    cudaGetSymbolAddress((void**)&h1,    g_h1);
    cudaGetSymbolAddress((void**)&o2,    g_o2);

    // 0) NHWC transpose of 2D features
    {
        int n = NVIEW*IMH*IMW;
        k_transpose<<<(n + 255)/256, 256>>>(feat2d);
    }
    // 1) back-project + sim for all 3 planes
    {
        int n = 3*PTS_PER_PLANE;
        k_backproject<<<(n + 127)/128, 128>>>(KRcam, origin);
    }
    // 2) conv1 (24->96, relu) and conv2 (96->288)
    {
        dim3 g1(144, 96/COCT, 3);
        k_conv3x3<C2, 96, true><<<g1, 128>>>(vol, w1, b1, h1);
        dim3 g2(144, 288/COCT, 3);
        k_conv3x3<96, 288, false><<<g2, 128>>>(h1, w2, b2, o2);
    }
    // 3) assemble feat output + mask
    {
        k_assemble<<<(FEAT_N + 255)/256, 256>>>(out, out_size);
        k_mask<<<(MASK_N + 255)/256, 256>>>(out, out_size);
    }
}